// round 1
// baseline (speedup 1.0000x reference)
#include <cuda_runtime.h>

#define SDIM 56
#define NCELL 3136
#define NITEM 6272
#define NCLS 20
#define IMG_STRIDE 94080
#define CONF_OFF 62720
#define COORD_OFF 68992
#define MAXOUT 30
#define NCAND 256
#define KEYBUF 2048

__global__ __launch_bounds__(256, 1) void detect_kernel(const float* __restrict__ in,
                                                        float* __restrict__ out)
{
    __shared__ float sc[NITEM];                 // item scores; later reused for candidate SoA
    __shared__ unsigned char scls[NITEM];       // item argmax class
    __shared__ unsigned long long keys[KEYBUF]; // also overlays 1024-bin int histogram
    __shared__ unsigned int wmask[8];
    __shared__ int s_binsel;
    __shared__ int s_cnt;
    __shared__ int s_pick;

    const int img = blockIdx.x;
    const int t = threadIdx.x;
    const float* base  = in + (long)img * IMG_STRIDE;
    const float* conf  = base + CONF_OFF;
    const float* coord = base + COORD_OFF;

    // ---------------- Phase A: decode per-item score (conf * max class prob) + class ----
    for (int cell = t; cell < NCELL; cell += 256) {
        const float4* cp = (const float4*)(base + cell * NCLS);
        float p[NCLS];
        #pragma unroll
        for (int k = 0; k < 5; ++k) {
            float4 v = cp[k];
            p[4*k+0] = v.x; p[4*k+1] = v.y; p[4*k+2] = v.z; p[4*k+3] = v.w;
        }
        float c0 = conf[cell*2+0];
        float c1 = conf[cell*2+1];
        float b0 = -1.0f, b1 = -1.0f;
        int a0 = 0, a1 = 0;
        #pragma unroll
        for (int c = 0; c < NCLS; ++c) {
            float v0 = c0 * p[c];
            float v1 = c1 * p[c];
            if (v0 > b0) { b0 = v0; a0 = c; }
            if (v1 > b1) { b1 = v1; a1 = c; }
        }
        float s0 = (b0 >= 0.1f) ? b0 : 0.0f;
        float s1 = (b1 >= 0.1f) ? b1 : 0.0f;
        sc[cell*2+0] = s0;
        sc[cell*2+1] = s1;
        scls[cell*2+0] = (unsigned char)a0;
        scls[cell*2+1] = (unsigned char)a1;
    }

    // ---------------- Phase B: 1024-bin histogram to find rank-256 threshold bin --------
    int* hist = (int*)keys;
    for (int k = t; k < 1024; k += 256) hist[k] = 0;
    __syncthreads();
    for (int i = t; i < NITEM; i += 256) {
        int b = (int)(sc[i] * 1024.0f);
        b = b < 0 ? 0 : (b > 1023 ? 1023 : b);
        atomicAdd(&hist[b], 1);
    }
    __syncthreads();
    if (t == 0) {
        int acc = 0, bstar = 0;
        for (int b = 1023; b >= 0; --b) {
            acc += hist[b];
            if (acc >= NCAND) { bstar = b; break; }
        }
        s_binsel = bstar;
        s_cnt = 0;
    }
    __syncthreads();
    const int bstar = s_binsel;

    // ---------------- Phase C: gather survivor keys (hist region now dead) -------------
    // key = score_bits(31b) << 13 | (8191 - idx): descending key order == lax.top_k order
    for (int i = t; i < NITEM; i += 256) {
        float s = sc[i];
        int b = (int)(s * 1024.0f);
        b = b < 0 ? 0 : (b > 1023 ? 1023 : b);
        if (b >= bstar) {
            int pos = atomicAdd(&s_cnt, 1);
            if (pos < KEYBUF) {
                unsigned long long key =
                    ((unsigned long long)__float_as_uint(s) << 13) |
                    (unsigned long long)(8191 - i);
                keys[pos] = key;
            }
        }
    }
    __syncthreads();
    int n = s_cnt; if (n > KEYBUF) n = KEYBUF;
    int np = NCAND; while (np < n) np <<= 1;
    for (int i = n + t; i < np; i += 256) keys[i] = 0ull;
    __syncthreads();

    // ---------------- Phase D: bitonic sort descending ---------------------------------
    for (int k = 2; k <= np; k <<= 1) {
        for (int j = k >> 1; j > 0; j >>= 1) {
            for (int i = t; i < np; i += 256) {
                int ixj = i ^ j;
                if (ixj > i) {
                    unsigned long long a = keys[i];
                    unsigned long long b2 = keys[ixj];
                    bool up = ((i & k) == 0);           // "up" segment: larger first
                    bool doswap = up ? (a < b2) : (a > b2);
                    if (doswap) { keys[i] = b2; keys[ixj] = a; }
                }
            }
            __syncthreads();
        }
    }

    // ---------------- Phase E: build 256 candidates (overlay SoA on sc) ----------------
    float* cy0  = sc;
    float* cx0  = sc + 256;
    float* cy1  = sc + 512;
    float* cx1  = sc + 768;
    float* cscv = sc + 1024;
    float* cclv = sc + 1280;
    {
        unsigned long long key = keys[t];
        int idx = 8191 - (int)(key & 0x1FFFull);
        float s = __uint_as_float((unsigned)(key >> 13));
        float y0 = 0.f, x0 = 0.f, y1 = 0.f, x1 = 0.f, cl = 0.f;
        if (idx < NITEM) {
            int cell = idx >> 1;
            int bb = idx & 1;
            int ci = cell / SDIM;
            int cj = cell - ci * SDIM;
            float4 cd = *(const float4*)(coord + ((long)cell * 2 + bb) * 4);
            float x = __fdiv_rn(cd.x + (float)cj, 56.0f);
            float y = __fdiv_rn(cd.y + (float)ci, 56.0f);
            float wh = (cd.z * cd.z) * 0.5f;   // exact *0.5
            float hh = (cd.w * cd.w) * 0.5f;
            y0 = y - hh; x0 = x - wh; y1 = y + hh; x1 = x + wh;
            cl = (float)scls[idx];
        } else {
            s = 0.0f;
        }
        cy0[t] = y0; cx0[t] = x0; cy1[t] = y1; cx1[t] = x1; cscv[t] = s; cclv[t] = cl;
    }
    __syncthreads();

    // ---------------- Phase F: greedy NMS, 30 rounds -----------------------------------
    const float my_y0 = cy0[t], my_x0 = cx0[t], my_y1 = cy1[t], my_x1 = cx1[t];
    const float my_area = __fmul_rn(fmaxf(my_y1 - my_y0, 0.0f), fmaxf(my_x1 - my_x0, 0.0f));
    bool valid = true;
    float* orow = out + (long)img * (MAXOUT * 6);

    for (int r = 0; r < MAXOUT; ++r) {
        unsigned m = __ballot_sync(0xFFFFFFFFu, valid);
        if ((t & 31) == 0) wmask[t >> 5] = m;
        __syncthreads();
        if (t == 0) {
            int p = -1;
            #pragma unroll
            for (int w = 0; w < 8; ++w) {
                unsigned mm = wmask[w];
                if (mm) { p = w * 32 + __ffs(mm) - 1; break; }
            }
            s_pick = p;
            float* o = orow + r * 6;
            if (p >= 0) {
                o[0] = cy0[p]; o[1] = cx0[p]; o[2] = cy1[p];
                o[3] = cx1[p]; o[4] = cscv[p]; o[5] = cclv[p];
            } else {
                o[0] = 0.f; o[1] = 0.f; o[2] = 0.f; o[3] = 0.f; o[4] = 0.f; o[5] = 0.f;
            }
        }
        __syncthreads();
        const int p = s_pick;
        if (p >= 0) {
            float py0 = cy0[p], px0 = cx0[p], py1 = cy1[p], px1 = cx1[p];
            float parea = __fmul_rn(fmaxf(py1 - py0, 0.0f), fmaxf(px1 - px0, 0.0f));
            float iy = fmaxf(0.0f, fminf(py1, my_y1) - fmaxf(py0, my_y0));
            float ix = fmaxf(0.0f, fminf(px1, my_x1) - fmaxf(px0, my_x0));
            float inter = __fmul_rn(iy, ix);
            float uni = parea + my_area - inter;
            float iou = (uni > 0.0f) ? __fdiv_rn(inter, uni) : 0.0f;
            if (iou > 0.4f) valid = false;
            if (t == p) valid = false;
        }
    }
}

extern "C" void kernel_launch(void* const* d_in, const int* in_sizes, int n_in,
                              void* d_out, int out_size)
{
    const float* in = (const float*)d_in[0];
    float* out = (float*)d_out;
    detect_kernel<<<256, 256>>>(in, out);
}